// round 9
// baseline (speedup 1.0000x reference)
#include <cuda_runtime.h>
#include <cuda_bf16.h>
#include <math.h>
#include <stdint.h>

#define Bdim 4096
#define Ldim 32
#define MIN_REAL (-3.4028234663852886e38f)
#define NBLK 256

// ---------------- scratch (device globals; no allocation allowed) ----------
__device__ float         g_h[2][(size_t)Bdim * 512];
__device__ __nv_bfloat16 g_abf[2][(size_t)Bdim * 768];     // [e | h] bf16
__device__ float         g_grz[(size_t)Bdim * 1024];
__device__ float         g_in[(size_t)Bdim * 512];
__device__ float         g_hn[(size_t)Bdim * 512];
__device__ float         g_logits[(size_t)Bdim * 512];
__device__ __nv_bfloat16 g_xbf[(size_t)Bdim * 512];
__device__ __nv_bfloat16 g_wrz[1024 * 768];
__device__ __nv_bfloat16 g_wihn[512 * 256];
__device__ __nv_bfloat16 g_whhn[512 * 512];
__device__ __nv_bfloat16 g_wo[512 * 512];
__device__ __nv_bfloat16 g_we[256 * 512];
__device__ __nv_bfloat16 g_wa[512 * 512];
__device__ float         g_brz[1024];
__device__ int           g_bar_count;
__device__ volatile int  g_bar_sense;

__device__ __forceinline__ float sigm(float x) { return 1.f / (1.f + expf(-x)); }

#define MMA_BF16(d, a, b) \
    asm volatile("mma.sync.aligned.m16n8k16.row.col.f32.bf16.bf16.f32 " \
        "{%0,%1,%2,%3}, {%4,%5,%6,%7}, {%8,%9}, {%0,%1,%2,%3};" \
        : "+f"((d)[0]), "+f"((d)[1]), "+f"((d)[2]), "+f"((d)[3]) \
        : "r"((a)[0]), "r"((a)[1]), "r"((a)[2]), "r"((a)[3]), \
          "r"((b)[0]), "r"((b)[1]))

#define LDM_X4(d, addr) \
    asm volatile("ldmatrix.sync.aligned.m8n8.x4.shared.b16 {%0,%1,%2,%3}, [%4];" \
        : "=r"((d)[0]), "=r"((d)[1]), "=r"((d)[2]), "=r"((d)[3]) : "r"(addr))

__device__ __forceinline__ void cp16(uint32_t dst, const void* src) {
    asm volatile("cp.async.cg.shared.global [%0], [%1], 16;" :: "r"(dst), "l"(src) : "memory");
}
#define CP_COMMIT  asm volatile("cp.async.commit_group;" ::: "memory")
#define CP_WAIT2   asm volatile("cp.async.wait_group 2;" ::: "memory")

#define SWZ(r, c) ((uint32_t)((((r) << 2) + ((c) ^ (((r) >> 1) & 3))) << 4))

// ---------------- global barrier (all NBLK blocks co-resident) --------------
__device__ __forceinline__ void gbar(int& sense) {
    __syncthreads();
    if (threadIdx.x == 0) {
        int s = sense ^ 1;
        sense = s;
        __threadfence();
        if (atomicAdd(&g_bar_count, 1) == NBLK - 1) {
            g_bar_count = 0;
            __threadfence();
            g_bar_sense = s;
        } else {
            while (g_bar_sense != s) __nanosleep(64);
        }
        __threadfence();
    }
    __syncthreads();
}

// ---------------- prep kernels ----------------------------------------------
__global__ void cvt_kernel(__nv_bfloat16* __restrict__ dst,
                           const float* __restrict__ src, int n) {
    int i = blockIdx.x * blockDim.x + threadIdx.x;
    if (i < n) dst[i] = __float2bfloat16_rn(src[i]);
}
__global__ void build_wrz_kernel(const float* __restrict__ Wih,
                                 const float* __restrict__ Whh) {
    int i = blockIdx.x * blockDim.x + threadIdx.x;   // 1024*768
    int g = i / 768, c = i % 768;
    float v = (c < 256) ? Wih[g * 256 + c] : Whh[g * 512 + (c - 256)];
    g_wrz[i] = __float2bfloat16_rn(v);
}
__global__ void build_brz_kernel(const float* __restrict__ bih,
                                 const float* __restrict__ bhh) {
    int i = blockIdx.x * blockDim.x + threadIdx.x;   // 1024
    g_brz[i] = bih[i] + bhh[i];
}
__global__ void init_e0_kernel(const float* __restrict__ sos) {
    int i = blockIdx.x * blockDim.x + threadIdx.x;   // B*256
    int b = i >> 8, c = i & 255;
    g_abf[0][(size_t)b * 768 + c] = __float2bfloat16_rn(sos[c]);
}

// =================== GEMM tile engine (device function) =====================
// MT = MFR*32 rows x 128 cols, 4 warps, warp tile (MT/2) x 64, K-block 32,
// 4-stage cp.async.cg, ldmatrix.x4. KB = K/32 (ends on stage 3 for KB in
// {8,16,24} so consecutive calls never collide on stage 0-2 prologue).
template<int MFR>
__device__ __forceinline__ void gemm_tile(
    char* dsm, int tid,
    const __nv_bfloat16* __restrict__ A, int lda,
    const __nv_bfloat16* __restrict__ W, int ldw, int KB,
    const float* __restrict__ bias,
    float* __restrict__ C, int ldc,
    __nv_bfloat16* __restrict__ Cbf, int ldcb,
    int m0, int n0)
{
    constexpr int AS = MFR * 2048;      // A stage bytes
    constexpr int SS = AS + 8192;       // stage stride
    const int wid = tid >> 5, lane = tid & 31;
    const int wm = wid & 1, wn = wid >> 1;
    const uint32_t smbase = (uint32_t)__cvta_generic_to_shared(dsm);

    float acc[MFR][8][4];
#pragma unroll
    for (int a_ = 0; a_ < MFR; a_++)
#pragma unroll
        for (int b_ = 0; b_ < 8; b_++)
#pragma unroll
            for (int c_ = 0; c_ < 4; c_++) acc[a_][b_][c_] = 0.f;

    const int cr = tid >> 2, cc = tid & 3;
    auto issue = [&](int kb, int s) {
        uint32_t sb = smbase + (uint32_t)s * SS;
#pragma unroll
        for (int it = 0; it < MFR; ++it) {
            int rr = cr + (it << 5);
            cp16(sb + SWZ(rr, cc), A + (size_t)(m0 + rr) * lda + (kb << 5) + (cc << 3));
        }
#pragma unroll
        for (int it = 0; it < 4; ++it) {
            int rr = cr + (it << 5);
            cp16(sb + AS + SWZ(rr, cc), W + (size_t)(n0 + rr) * ldw + (kb << 5) + (cc << 3));
        }
    };
    const int arow0 = wm * (MFR << 4) + (lane & 7) + (((lane >> 3) & 1) << 3);
    const int acb   = (lane >> 4) & 1;
    const int nrow0 = (wn << 6) + (lane & 7) + (((lane >> 4) & 1) << 3);
    const int bcb   = (lane >> 3) & 1;

    issue(0, 0); CP_COMMIT;
    issue(1, 1); CP_COMMIT;
    issue(2, 2); CP_COMMIT;
#pragma unroll 1
    for (int kb = 0; kb < KB; ++kb) {
        CP_WAIT2;
        __syncthreads();
        if (kb + 3 < KB) issue(kb + 3, (kb + 3) & 3);
        CP_COMMIT;
        uint32_t ab = smbase + (uint32_t)(kb & 3) * SS, bb = ab + AS;
#pragma unroll
        for (int ks = 0; ks < 2; ++ks) {
            uint32_t afr[MFR][4];
#pragma unroll
            for (int mt = 0; mt < MFR; ++mt)
                LDM_X4(afr[mt], ab + SWZ(arow0 + (mt << 4), (ks << 1) + acb));
            uint32_t bfr[8][2];
#pragma unroll
            for (int p = 0; p < 4; ++p) {
                uint32_t t4[4];
                LDM_X4(t4, bb + SWZ(nrow0 + (p << 4), (ks << 1) + bcb));
                bfr[2 * p][0] = t4[0]; bfr[2 * p][1] = t4[1];
                bfr[2 * p + 1][0] = t4[2]; bfr[2 * p + 1][1] = t4[3];
            }
#pragma unroll
            for (int mt = 0; mt < MFR; ++mt)
#pragma unroll
                for (int nt = 0; nt < 8; ++nt)
                    MMA_BF16(acc[mt][nt], afr[mt], bfr[nt]);
        }
    }

#pragma unroll
    for (int mt = 0; mt < MFR; ++mt) {
#pragma unroll
        for (int nt = 0; nt < 8; ++nt) {
            int row = m0 + wm * (MFR << 4) + (mt << 4) + (lane >> 2);
            int col = n0 + (wn << 6) + (nt << 3) + ((lane & 3) << 1);
            float2 bv = *(const float2*)&bias[col];
            float2 o0 = {acc[mt][nt][0] + bv.x, acc[mt][nt][1] + bv.y};
            float2 o1 = {acc[mt][nt][2] + bv.x, acc[mt][nt][3] + bv.y};
            if (C) {
                *(float2*)&C[(size_t)row * ldc + col] = o0;
                *(float2*)&C[(size_t)(row + 8) * ldc + col] = o1;
            }
            if (Cbf) {
                __nv_bfloat162 p0 = {__float2bfloat16_rn(o0.x), __float2bfloat16_rn(o0.y)};
                __nv_bfloat162 p1 = {__float2bfloat16_rn(o1.x), __float2bfloat16_rn(o1.y)};
                *(__nv_bfloat162*)&Cbf[(size_t)row * ldcb + col] = p0;
                *(__nv_bfloat162*)&Cbf[(size_t)(row + 8) * ldcb + col] = p1;
            }
        }
    }
}

// ======================= persistent whole-loop kernel =======================
__global__ __launch_bounds__(128, 2) void persist(
    const float* __restrict__ noise, float* __restrict__ out, float* __restrict__ ent,
    const __nv_bfloat16* __restrict__ xbf, const __nv_bfloat16* __restrict__ wa,
    const float* __restrict__ ba,
    const __nv_bfloat16* __restrict__ wrz, const float* __restrict__ brz,
    const __nv_bfloat16* __restrict__ wihn, const float* __restrict__ bihn,
    const __nv_bfloat16* __restrict__ whhn, const float* __restrict__ bhhn,
    const __nv_bfloat16* __restrict__ wo, const float* __restrict__ bo,
    const __nv_bfloat16* __restrict__ we, const float* __restrict__ be,
    float* __restrict__ hbuf0, float* __restrict__ hbuf1,
    __nv_bfloat16* __restrict__ abf0, __nv_bfloat16* __restrict__ abf1,
    float* __restrict__ grz, float* __restrict__ inb, float* __restrict__ hnb,
    float* __restrict__ lbuf)
{
    extern __shared__ __align__(1024) char dsm[];
    const int tid = threadIdx.x, bid = blockIdx.x;
    const int wid = tid >> 5, lane = tid & 31;
    int sense = 0;

    // ---- h0 = x @ Wa^T + ba (128 jobs: 32 m-tiles x 4 n-tiles) ----
    if (bid < 128)
        gemm_tile<4>(dsm, tid, xbf, 512, wa, 512, 16, ba,
                     hbuf0, 512, abf0 + 256, 768, (bid >> 2) << 7, (bid & 3) << 7);
    gbar(sense);

#pragma unroll 1
    for (int l = 0; l < Ldim; ++l) {
        const __nv_bfloat16* Ain = (l & 1) ? abf1 : abf0;
        __nv_bfloat16* Anxt      = (l & 1) ? abf0 : abf1;
        const float* hin         = (l & 1) ? hbuf1 : hbuf0;
        float* hout              = (l & 1) ? hbuf0 : hbuf1;

        // ---- gates: 512 jobs (rz 256, i_n 128, h_n 128); 2 per block ----
#pragma unroll 1
        for (int q = 0; q < 2; ++q) {
            int j = bid + (q << 8);
            if (j < 256) {
                gemm_tile<4>(dsm, tid, Ain, 768, wrz, 768, 24, brz,
                             grz, 1024, (__nv_bfloat16*)0, 0,
                             (j >> 3) << 7, (j & 7) << 7);
            } else if (j < 384) {
                int t = j - 256;
                gemm_tile<4>(dsm, tid, Ain, 768, wihn, 256, 8, bihn,
                             inb, 512, (__nv_bfloat16*)0, 0,
                             (t >> 2) << 7, (t & 3) << 7);
            } else {
                int t = j - 384;
                gemm_tile<4>(dsm, tid, Ain + 256, 768, whhn, 512, 16, bhhn,
                             hnb, 512, (__nv_bfloat16*)0, 0,
                             (t >> 2) << 7, (t & 3) << 7);
            }
        }
        gbar(sense);

        // ---- gru elementwise: 2048 float4 rows per block ----
#pragma unroll 1
        for (int t = 0; t < 16; ++t) {
            int i = (bid << 11) + (t << 7) + tid;
            int b = i >> 7, jq = i & 127;
            float4 gr = __ldcg((const float4*)grz + (size_t)b * 256 + jq);
            float4 gz = __ldcg((const float4*)grz + (size_t)b * 256 + 128 + jq);
            float4 gi = __ldcg((const float4*)inb + (size_t)b * 128 + jq);
            float4 gh = __ldcg((const float4*)hnb + (size_t)b * 128 + jq);
            float4 h  = __ldcg((const float4*)hin + (size_t)b * 128 + jq);
            float4 o;
            { float r = sigm(gr.x), z = sigm(gz.x);
              o.x = (1.f - z) * tanhf(gi.x + r * gh.x) + z * h.x; }
            { float r = sigm(gr.y), z = sigm(gz.y);
              o.y = (1.f - z) * tanhf(gi.y + r * gh.y) + z * h.y; }
            { float r = sigm(gr.z), z = sigm(gz.z);
              o.z = (1.f - z) * tanhf(gi.z + r * gh.z) + z * h.z; }
            { float r = sigm(gr.w), z = sigm(gz.w);
              o.w = (1.f - z) * tanhf(gi.w + r * gh.w) + z * h.w; }
            *((float4*)hout + (size_t)b * 128 + jq) = o;
            __nv_bfloat162 p0 = {__float2bfloat16_rn(o.x), __float2bfloat16_rn(o.y)};
            __nv_bfloat162 p1 = {__float2bfloat16_rn(o.z), __float2bfloat16_rn(o.w)};
            __nv_bfloat162* dst = (__nv_bfloat162*)(Anxt + (size_t)b * 768 + 256 + (jq << 2));
            dst[0] = p0; dst[1] = p1;
        }
        gbar(sense);

        // ---- logits: 256 jobs of 64x128 (64 m-tiles x 4 n-tiles) ----
        gemm_tile<2>(dsm, tid, Anxt + 256, 768, wo, 512, 16, bo,
                     lbuf, 512, (__nv_bfloat16*)0, 0,
                     (bid >> 2) << 6, (bid & 3) << 7);
        gbar(sense);

        // ---- softmax (16 rows) + emb GEMM (16x256, K=512) per block ----
        {
            const int b0 = bid << 4;
            const uint32_t smbase = (uint32_t)__cvta_generic_to_shared(dsm);
            const uint32_t sB = smbase + 16384u;
            const int acb = (lane >> 4) & 1, bcb = (lane >> 3) & 1;
            const int cr = tid >> 2, cc = tid & 3;

            auto issueWe = [&](int kb, int s) {
                uint32_t sb = sB + ((uint32_t)s << 14);
#pragma unroll
                for (int it = 0; it < 8; ++it) {
                    int rr = cr + (it << 5);
                    cp16(sb + SWZ(rr, cc), we + (size_t)rr * 512 + (kb << 5) + (cc << 3));
                }
            };
            issueWe(0, 0); CP_COMMIT;
            issueWe(1, 1); CP_COMMIT;
            issueWe(2, 2); CP_COMMIT;

            // softmax: warp wid handles rows wid*4 .. wid*4+3
#pragma unroll 1
            for (int rr = 0; rr < 4; ++rr) {
                int row = (wid << 2) + rr;
                int gb = b0 + row;
                const float* lrow = lbuf + (size_t)gb * 512;
                const float* urow = noise + (size_t)l * Bdim * 512 + (size_t)gb * 512;
                float v[16];
                float m = -INFINITY;
#pragma unroll
                for (int i = 0; i < 16; ++i) {
                    float uu = __ldg(urow + lane + 32 * i);
                    float g = -logf(-logf(uu));
                    v[i] = __ldcg(lrow + lane + 32 * i) + g;
                    m = fmaxf(m, v[i]);
                }
#pragma unroll
                for (int o = 16; o; o >>= 1) m = fmaxf(m, __shfl_xor_sync(0xffffffffu, m, o));
                float sum = 0.f;
#pragma unroll
                for (int i = 0; i < 16; ++i) { v[i] = expf(v[i] - m); sum += v[i]; }
#pragma unroll
                for (int o = 16; o; o >>= 1) sum += __shfl_xor_sync(0xffffffffu, sum, o);
                float inv = 1.f / sum;
                float eacc = 0.f;
                float* srow = out + ((size_t)gb * Ldim + l) * 512;
#pragma unroll
                for (int i = 0; i < 16; ++i) {
                    float p = v[i] * inv;
                    srow[lane + 32 * i] = p;
                    uint32_t off = ((uint32_t)i << 10) + SWZ(row, (lane >> 3) & 3)
                                   + ((lane & 7) << 1);
                    *(__nv_bfloat16*)(dsm + off) = __float2bfloat16_rn(p);
                    float t = fmaxf(log2f(p), MIN_REAL);
                    eacc -= p * t;
                }
#pragma unroll
                for (int o = 16; o; o >>= 1) eacc += __shfl_xor_sync(0xffffffffu, eacc, o);
                if (lane == 0) ent[(size_t)gb * Ldim + l] = eacc;
            }
            __syncthreads();

            // emb GEMM: A = sample slabs (16 rows), B = We (N=256), K=512
            float acc2[8][4];
#pragma unroll
            for (int b_ = 0; b_ < 8; b_++)
#pragma unroll
                for (int c_ = 0; c_ < 4; c_++) acc2[b_][c_] = 0.f;
            const int arowe = (lane & 7) + (((lane >> 3) & 1) << 3);
            const int nrowe = (wid << 6) + (lane & 7) + (((lane >> 4) & 1) << 3);
#pragma unroll 1
            for (int kb = 0; kb < 16; ++kb) {
                CP_WAIT2;
                __syncthreads();
                if (kb + 3 < 16) issueWe(kb + 3, (kb + 3) & 3);
                CP_COMMIT;
                uint32_t ab = smbase + ((uint32_t)kb << 10);
                uint32_t bb = sB + ((uint32_t)(kb & 3) << 14);
#pragma unroll
                for (int ks = 0; ks < 2; ++ks) {
                    uint32_t afr[4];
                    LDM_X4(afr, ab + SWZ(arowe, (ks << 1) + acb));
                    uint32_t bfr[8][2];
#pragma unroll
                    for (int p = 0; p < 4; ++p) {
                        uint32_t t4[4];
                        LDM_X4(t4, bb + SWZ(nrowe + (p << 4), (ks << 1) + bcb));
                        bfr[2 * p][0] = t4[0]; bfr[2 * p][1] = t4[1];
                        bfr[2 * p + 1][0] = t4[2]; bfr[2 * p + 1][1] = t4[3];
                    }
#pragma unroll
                    for (int nt = 0; nt < 8; ++nt)
                        MMA_BF16(acc2[nt], afr, bfr[nt]);
                }
            }
#pragma unroll
            for (int nt = 0; nt < 8; ++nt) {
                int col = (wid << 6) + (nt << 3) + ((lane & 3) << 1);
                int row = b0 + (lane >> 2);
                float2 bv = *(const float2*)&be[col];
                __nv_bfloat162 p0 = {__float2bfloat16_rn(acc2[nt][0] + bv.x),
                                     __float2bfloat16_rn(acc2[nt][1] + bv.y)};
                __nv_bfloat162 p1 = {__float2bfloat16_rn(acc2[nt][2] + bv.x),
                                     __float2bfloat16_rn(acc2[nt][3] + bv.y)};
                *(__nv_bfloat162*)&Anxt[(size_t)row * 768 + col] = p0;
                *(__nv_bfloat162*)&Anxt[(size_t)(row + 8) * 768 + col] = p1;
            }
        }
        gbar(sense);
    }
}

// ======================= host launcher ======================================
extern "C" void kernel_launch(void* const* d_in, const int* in_sizes, int n_in,
                              void* d_out, int out_size)
{
    const float* x       = (const float*)d_in[0];
    const float* noise   = (const float*)d_in[1];
    const float* W_agent = (const float*)d_in[2];
    const float* b_agent = (const float*)d_in[3];
    const float* W_ih    = (const float*)d_in[4];
    const float* W_hh    = (const float*)d_in[5];
    const float* b_ih    = (const float*)d_in[6];
    const float* b_hh    = (const float*)d_in[7];
    const float* W_out   = (const float*)d_in[8];
    const float* b_out   = (const float*)d_in[9];
    const float* W_emb   = (const float*)d_in[10];
    const float* b_emb   = (const float*)d_in[11];
    const float* sos     = (const float*)d_in[12];

    float* out = (float*)d_out;
    float* ent = out + (size_t)Bdim * Ldim * 512;

    float *hbuf0, *grz, *inb, *hnb, *lbuf, *brz;
    __nv_bfloat16 *abf0, *xbf, *wrz, *wihn, *whhn, *wo, *we, *wa;
    cudaGetSymbolAddress((void**)&hbuf0, g_h);
    float* hbuf1 = hbuf0 + (size_t)Bdim * 512;
    cudaGetSymbolAddress((void**)&abf0, g_abf);
    __nv_bfloat16* abf1 = abf0 + (size_t)Bdim * 768;
    cudaGetSymbolAddress((void**)&grz, g_grz);
    cudaGetSymbolAddress((void**)&inb, g_in);
    cudaGetSymbolAddress((void**)&hnb, g_hn);
    cudaGetSymbolAddress((void**)&lbuf, g_logits);
    cudaGetSymbolAddress((void**)&xbf, g_xbf);
    cudaGetSymbolAddress((void**)&wrz, g_wrz);
    cudaGetSymbolAddress((void**)&wihn, g_wihn);
    cudaGetSymbolAddress((void**)&whhn, g_whhn);
    cudaGetSymbolAddress((void**)&wo, g_wo);
    cudaGetSymbolAddress((void**)&we, g_we);
    cudaGetSymbolAddress((void**)&wa, g_wa);
    cudaGetSymbolAddress((void**)&brz, g_brz);

    cudaFuncSetAttribute(persist, cudaFuncAttributeMaxDynamicSharedMemorySize, 81920);

    // ---- one-time prep ----
    build_wrz_kernel<<<(1024 * 768) / 256, 256>>>(W_ih, W_hh);
    build_brz_kernel<<<4, 256>>>(b_ih, b_hh);
    cvt_kernel<<<(512 * 256) / 256, 256>>>(wihn, W_ih + 1024 * 256, 512 * 256);
    cvt_kernel<<<(512 * 512) / 256, 256>>>(whhn, W_hh + 1024 * 512, 512 * 512);
    cvt_kernel<<<(512 * 512) / 256, 256>>>(wo, W_out, 512 * 512);
    cvt_kernel<<<(256 * 512) / 256, 256>>>(we, W_emb, 256 * 512);
    cvt_kernel<<<(512 * 512) / 256, 256>>>(wa, W_agent, 512 * 512);
    cvt_kernel<<<(Bdim * 512) / 256, 256>>>(xbf, x, Bdim * 512);
    init_e0_kernel<<<(Bdim * 256) / 256, 256>>>(sos);

    // ---- whole recurrence in one persistent kernel ----
    persist<<<NBLK, 128, 81920>>>(
        noise, out, ent,
        xbf, wa, b_agent,
        wrz, brz,
        wihn, b_ih + 1024,
        whhn, b_hh + 1024,
        wo, b_out,
        we, b_emb,
        hbuf0, hbuf1, abf0, abf1,
        grz, inb, hnb, lbuf);

    (void)in_sizes; (void)n_in; (void)out_size;
}

// round 10
// speedup vs baseline: 1.1194x; 1.1194x over previous
#include <cuda_runtime.h>
#include <cuda_bf16.h>
#include <math.h>
#include <stdint.h>

#define Bdim 4096
#define Ldim 32
#define MIN_REAL (-3.4028234663852886e38f)
#define LOG2E 1.4426950408889634f

// ---------------- scratch (device globals; no allocation allowed) ----------
__device__ float         g_h[2][(size_t)Bdim * 512];       // fp32 hidden
__device__ __nv_bfloat16 g_abf[2][(size_t)Bdim * 768];     // [e | h] bf16
__device__ float         g_grz[(size_t)Bdim * 1024];
__device__ float         g_in[(size_t)Bdim * 512];
__device__ float         g_logits[(size_t)Bdim * 512];
__device__ __nv_bfloat16 g_sbf[(size_t)Bdim * 512];
__device__ __nv_bfloat16 g_xbf[(size_t)Bdim * 512];
__device__ __nv_bfloat16 g_wrz[1024 * 768];
__device__ __nv_bfloat16 g_wihn[512 * 256];
__device__ __nv_bfloat16 g_whhn[512 * 512];
__device__ __nv_bfloat16 g_wo[512 * 512];
__device__ __nv_bfloat16 g_we[256 * 512];
__device__ __nv_bfloat16 g_wa[512 * 512];
__device__ float         g_brz[1024];

__device__ __forceinline__ float sigm(float x) { return 1.f / (1.f + expf(-x)); }

#define MMA_BF16(d, a, b) \
    asm volatile("mma.sync.aligned.m16n8k16.row.col.f32.bf16.bf16.f32 " \
        "{%0,%1,%2,%3}, {%4,%5,%6,%7}, {%8,%9}, {%0,%1,%2,%3};" \
        : "+f"((d)[0]), "+f"((d)[1]), "+f"((d)[2]), "+f"((d)[3]) \
        : "r"((a)[0]), "r"((a)[1]), "r"((a)[2]), "r"((a)[3]), \
          "r"((b)[0]), "r"((b)[1]))

#define LDM_X4(d, addr) \
    asm volatile("ldmatrix.sync.aligned.m8n8.x4.shared.b16 {%0,%1,%2,%3}, [%4];" \
        : "=r"((d)[0]), "=r"((d)[1]), "=r"((d)[2]), "=r"((d)[3]) : "r"(addr))

__device__ __forceinline__ void cp16(uint32_t dst, const void* src) {
    asm volatile("cp.async.cg.shared.global [%0], [%1], 16;" :: "r"(dst), "l"(src) : "memory");
}
#define CP_COMMIT  asm volatile("cp.async.commit_group;" ::: "memory")
#define CP_WAIT2   asm volatile("cp.async.wait_group 2;" ::: "memory")

#define SWZ(r, c) ((uint32_t)((((r) << 2) + ((c) ^ (((r) >> 1) & 3))) << 4))

// ---------------- prep kernels ----------------------------------------------
__global__ void cvt_kernel(__nv_bfloat16* __restrict__ dst,
                           const float* __restrict__ src, int n) {
    int i = blockIdx.x * blockDim.x + threadIdx.x;
    if (i < n) dst[i] = __float2bfloat16_rn(src[i]);
}
__global__ void build_wrz_kernel(const float* __restrict__ Wih,
                                 const float* __restrict__ Whh) {
    int i = blockIdx.x * blockDim.x + threadIdx.x;   // 1024*768
    int g = i / 768, c = i % 768;
    float v = (c < 256) ? Wih[g * 256 + c] : Whh[g * 512 + (c - 256)];
    g_wrz[i] = __float2bfloat16_rn(v);
}
__global__ void build_brz_kernel(const float* __restrict__ bih,
                                 const float* __restrict__ bhh) {
    int i = blockIdx.x * blockDim.x + threadIdx.x;   // 1024
    g_brz[i] = bih[i] + bhh[i];
}
__global__ void init_e0_kernel(const float* __restrict__ sos) {
    int i = blockIdx.x * blockDim.x + threadIdx.x;   // B*256
    int b = i >> 8, c = i & 255;
    g_abf[0][(size_t)b * 768 + c] = __float2bfloat16_rn(sos[c]);
}

// =================== GEMM mainloop (device function) ========================
// MFR*32 rows x 128 cols, 4 warps, warp tile (MFR*16)x64 x2m, K-block 32,
// 4-stage cp.async.cg pipeline, ldmatrix.x4.
template<int MFR>
__device__ __forceinline__ void gemm_mainloop(
    char* smem, int tid,
    const __nv_bfloat16* __restrict__ A, int lda,
    const __nv_bfloat16* __restrict__ W, int ldw, int KB,
    int m0, int n0, float acc[MFR][8][4])
{
    constexpr int AS = MFR * 2048;
    constexpr int SS = AS + 8192;
    const int wid = tid >> 5, lane = tid & 31;
    const int wm = wid & 1, wn = wid >> 1;
    const uint32_t smbase = (uint32_t)__cvta_generic_to_shared(smem);

#pragma unroll
    for (int a_ = 0; a_ < MFR; a_++)
#pragma unroll
        for (int b_ = 0; b_ < 8; b_++)
#pragma unroll
            for (int c_ = 0; c_ < 4; c_++) acc[a_][b_][c_] = 0.f;

    const int cr = tid >> 2, cc = tid & 3;
    auto issue = [&](int kb, int s) {
        uint32_t sb = smbase + (uint32_t)s * SS;
#pragma unroll
        for (int it = 0; it < MFR; ++it) {
            int rr = cr + (it << 5);
            cp16(sb + SWZ(rr, cc), A + (size_t)(m0 + rr) * lda + (kb << 5) + (cc << 3));
        }
#pragma unroll
        for (int it = 0; it < 4; ++it) {
            int rr = cr + (it << 5);
            cp16(sb + AS + SWZ(rr, cc), W + (size_t)(n0 + rr) * ldw + (kb << 5) + (cc << 3));
        }
    };
    const int arow0 = wm * (MFR << 4) + (lane & 7) + (((lane >> 3) & 1) << 3);
    const int acb   = (lane >> 4) & 1;
    const int nrow0 = (wn << 6) + (lane & 7) + (((lane >> 4) & 1) << 3);
    const int bcb   = (lane >> 3) & 1;

    issue(0, 0); CP_COMMIT;
    issue(1, 1); CP_COMMIT;
    issue(2, 2); CP_COMMIT;
#pragma unroll 1
    for (int kb = 0; kb < KB; ++kb) {
        CP_WAIT2;
        __syncthreads();
        if (kb + 3 < KB) issue(kb + 3, (kb + 3) & 3);
        CP_COMMIT;
        uint32_t ab = smbase + (uint32_t)(kb & 3) * SS, bb = ab + AS;
#pragma unroll
        for (int ks = 0; ks < 2; ++ks) {
            uint32_t afr[MFR][4];
#pragma unroll
            for (int mt = 0; mt < MFR; ++mt)
                LDM_X4(afr[mt], ab + SWZ(arow0 + (mt << 4), (ks << 1) + acb));
            uint32_t bfr[8][2];
#pragma unroll
            for (int p = 0; p < 4; ++p) {
                uint32_t t4[4];
                LDM_X4(t4, bb + SWZ(nrow0 + (p << 4), (ks << 1) + bcb));
                bfr[2 * p][0] = t4[0]; bfr[2 * p][1] = t4[1];
                bfr[2 * p + 1][0] = t4[2]; bfr[2 * p + 1][1] = t4[3];
            }
#pragma unroll
            for (int mt = 0; mt < MFR; ++mt)
#pragma unroll
                for (int nt = 0; nt < 8; ++nt)
                    MMA_BF16(acc[mt][nt], afr[mt], bfr[nt]);
        }
    }
}

// ======================= generic bf16 GEMM ==================================
template<int MFR>
__global__ __launch_bounds__(128, 2) void gemm_bf(
    const __nv_bfloat16* __restrict__ A, int lda,
    const __nv_bfloat16* __restrict__ W, int K,
    const float* __restrict__ bias,
    float* __restrict__ C, int ldc,
    __nv_bfloat16* __restrict__ Cbf, int ldcb)
{
    __shared__ __align__(1024) char smem[(MFR * 2048 + 8192) * 4];
    const int tid = threadIdx.x, wid = tid >> 5, lane = tid & 31;
    const int wm = wid & 1, wn = wid >> 1;
    const int m0 = blockIdx.y * (MFR << 5), n0 = blockIdx.x << 7;

    float acc[MFR][8][4];
    gemm_mainloop<MFR>(smem, tid, A, lda, W, K, K >> 5, m0, n0, acc);

#pragma unroll
    for (int mt = 0; mt < MFR; ++mt) {
#pragma unroll
        for (int nt = 0; nt < 8; ++nt) {
            int row = m0 + wm * (MFR << 4) + (mt << 4) + (lane >> 2);
            int col = n0 + (wn << 6) + (nt << 3) + ((lane & 3) << 1);
            float2 bv = *(const float2*)&bias[col];
            float2 o0 = {acc[mt][nt][0] + bv.x, acc[mt][nt][1] + bv.y};
            float2 o1 = {acc[mt][nt][2] + bv.x, acc[mt][nt][3] + bv.y};
            if (C) {
                *(float2*)&C[(size_t)row * ldc + col] = o0;
                *(float2*)&C[(size_t)(row + 8) * ldc + col] = o1;
            }
            if (Cbf) {
                __nv_bfloat162 p0 = {__float2bfloat16_rn(o0.x), __float2bfloat16_rn(o0.y)};
                __nv_bfloat162 p1 = {__float2bfloat16_rn(o1.x), __float2bfloat16_rn(o1.y)};
                *(__nv_bfloat162*)&Cbf[(size_t)row * ldcb + col] = p0;
                *(__nv_bfloat162*)&Cbf[(size_t)(row + 8) * ldcb + col] = p1;
            }
        }
    }
}

// ================= h_n GEMM with fused GRU update ===========================
// 64x128 tile; acc = h @ Whh_n^T; epilogue stages h_n+b in smem, then
// n = tanh(i_n + r*h_n); h' = (1-z)*n + z*h  -> hout fp32 + Anxt h-slot bf16.
__global__ __launch_bounds__(128, 2) void gemm_hn_gru(
    const __nv_bfloat16* __restrict__ A,    // h bf16 (ld 768)
    const __nv_bfloat16* __restrict__ W,    // Whh_n [512,512]
    const float* __restrict__ bias,         // b_hh_n
    const float* __restrict__ grz,          // [B,1024] r|z (biased)
    const float* __restrict__ inb,          // [B,512] i_n (+b_ih_n)
    const float* __restrict__ hin,          // [B,512] fp32
    float* __restrict__ hout,
    __nv_bfloat16* __restrict__ habf)       // Anxt base; h at +256, ld 768
{
    __shared__ __align__(1024) char smem[(2 * 2048 + 8192) * 4];   // 48K
    const int tid = threadIdx.x, wid = tid >> 5, lane = tid & 31;
    const int wm = wid & 1, wn = wid >> 1;
    const int m0 = blockIdx.y << 6, n0 = blockIdx.x << 7;

    float acc[2][8][4];
    gemm_mainloop<2>(smem, tid, A, 768, W, 512, 16, m0, n0, acc);

    __syncthreads();
    float* st = (float*)smem;               // [64][132]
#pragma unroll
    for (int mt = 0; mt < 2; ++mt) {
#pragma unroll
        for (int nt = 0; nt < 8; ++nt) {
            int rl = (wm << 5) + (mt << 4) + (lane >> 2);
            int col = (wn << 6) + (nt << 3) + ((lane & 3) << 1);
            float2 bv = *(const float2*)&bias[n0 + col];
            float2 s0 = {acc[mt][nt][0] + bv.x, acc[mt][nt][1] + bv.y};
            float2 s1 = {acc[mt][nt][2] + bv.x, acc[mt][nt][3] + bv.y};
            *(float2*)&st[rl * 132 + col] = s0;
            *(float2*)&st[(rl + 8) * 132 + col] = s1;
        }
    }
    __syncthreads();

#pragma unroll
    for (int t = 0; t < 16; ++t) {
        int idx = tid + (t << 7);
        int r = idx >> 5, q = idx & 31;
        int rg = m0 + r, jg = n0 + (q << 2);
        float4 hn = *(float4*)&st[r * 132 + (q << 2)];
        float4 rr = *(const float4*)&grz[(size_t)rg * 1024 + jg];
        float4 zz = *(const float4*)&grz[(size_t)rg * 1024 + 512 + jg];
        float4 ii = *(const float4*)&inb[(size_t)rg * 512 + jg];
        float4 hh = *(const float4*)&hin[(size_t)rg * 512 + jg];
        float4 o;
        { float rs = sigm(rr.x), zs = sigm(zz.x);
          o.x = (1.f - zs) * tanhf(ii.x + rs * hn.x) + zs * hh.x; }
        { float rs = sigm(rr.y), zs = sigm(zz.y);
          o.y = (1.f - zs) * tanhf(ii.y + rs * hn.y) + zs * hh.y; }
        { float rs = sigm(rr.z), zs = sigm(zz.z);
          o.z = (1.f - zs) * tanhf(ii.z + rs * hn.z) + zs * hh.z; }
        { float rs = sigm(rr.w), zs = sigm(zz.w);
          o.w = (1.f - zs) * tanhf(ii.w + rs * hn.w) + zs * hh.w; }
        *(float4*)&hout[(size_t)rg * 512 + jg] = o;
        __nv_bfloat162 p0 = {__float2bfloat16_rn(o.x), __float2bfloat16_rn(o.y)};
        __nv_bfloat162 p1 = {__float2bfloat16_rn(o.z), __float2bfloat16_rn(o.w)};
        __nv_bfloat162* dst = (__nv_bfloat162*)(habf + (size_t)rg * 768 + 256 + jg);
        dst[0] = p0; dst[1] = p1;
    }
}

// ============= base-2 gumbel softmax + analytic entropy =====================
// y = l*log2e - log2(-log2 u)  (const shift vs ref; cancels in softmax)
// H  = log2(S) - sum(e*w)/S  with w = y - m  (== -sum p*log2 p exactly)
__global__ __launch_bounds__(256) void softmax_kernel(
    const float* __restrict__ logits, const float* __restrict__ u,
    float* __restrict__ seq, float* __restrict__ ent,
    __nv_bfloat16* __restrict__ sbf, int l)
{
    const int warp = threadIdx.x >> 5, lane = threadIdx.x & 31;
    const int b = blockIdx.x * 8 + warp;
    const float* lrow = logits + (size_t)b * 512;
    const float* urow = u + (size_t)b * 512;

    float v[16];
    float m = -INFINITY;
#pragma unroll
    for (int i = 0; i < 16; i++) {
        float uu = __ldg(urow + lane + 32 * i);
        float t = -__log2f(uu);                  // -log2(u) > 0
        float s = __log2f(t);
        v[i] = fmaf(lrow[lane + 32 * i], LOG2E, -s);
        m = fmaxf(m, v[i]);
    }
#pragma unroll
    for (int o = 16; o; o >>= 1) m = fmaxf(m, __shfl_xor_sync(0xffffffffu, m, o));

    float sum = 0.f, ews = 0.f;
#pragma unroll
    for (int i = 0; i < 16; i++) {
        float w = v[i] - m;
        float e = exp2f(w);
        v[i] = e;
        sum += e;
        ews = fmaf(e, w, ews);
    }
#pragma unroll
    for (int o = 16; o; o >>= 1) {
        sum += __shfl_xor_sync(0xffffffffu, sum, o);
        ews += __shfl_xor_sync(0xffffffffu, ews, o);
    }

    float inv = 1.f / sum;
    float* srow = seq + ((size_t)b * Ldim + l) * 512;
    __nv_bfloat16* brow = sbf + (size_t)b * 512;
#pragma unroll
    for (int i = 0; i < 16; i++) {
        float p = v[i] * inv;
        srow[lane + 32 * i] = p;
        brow[lane + 32 * i] = __float2bfloat16_rn(p);
    }
    if (lane == 0)
        ent[(size_t)b * Ldim + l] = __log2f(sum) - ews * inv;
}

// ======================= host launcher ======================================
extern "C" void kernel_launch(void* const* d_in, const int* in_sizes, int n_in,
                              void* d_out, int out_size)
{
    const float* x       = (const float*)d_in[0];
    const float* noise   = (const float*)d_in[1];
    const float* W_agent = (const float*)d_in[2];
    const float* b_agent = (const float*)d_in[3];
    const float* W_ih    = (const float*)d_in[4];
    const float* W_hh    = (const float*)d_in[5];
    const float* b_ih    = (const float*)d_in[6];
    const float* b_hh    = (const float*)d_in[7];
    const float* W_out   = (const float*)d_in[8];
    const float* b_out   = (const float*)d_in[9];
    const float* W_emb   = (const float*)d_in[10];
    const float* b_emb   = (const float*)d_in[11];
    const float* sos     = (const float*)d_in[12];

    float* out = (float*)d_out;
    float* ent = out + (size_t)Bdim * Ldim * 512;

    float *hbuf0, *grz, *inb, *lbuf, *brz;
    __nv_bfloat16 *abf0, *sbf, *xbf, *wrz, *wihn, *whhn, *wo, *we, *wa;
    cudaGetSymbolAddress((void**)&hbuf0, g_h);
    float* hbuf1 = hbuf0 + (size_t)Bdim * 512;
    cudaGetSymbolAddress((void**)&abf0, g_abf);
    __nv_bfloat16* abf1 = abf0 + (size_t)Bdim * 768;
    cudaGetSymbolAddress((void**)&grz, g_grz);
    cudaGetSymbolAddress((void**)&inb, g_in);
    cudaGetSymbolAddress((void**)&lbuf, g_logits);
    cudaGetSymbolAddress((void**)&sbf, g_sbf);
    cudaGetSymbolAddress((void**)&xbf, g_xbf);
    cudaGetSymbolAddress((void**)&wrz, g_wrz);
    cudaGetSymbolAddress((void**)&wihn, g_wihn);
    cudaGetSymbolAddress((void**)&whhn, g_whhn);
    cudaGetSymbolAddress((void**)&wo, g_wo);
    cudaGetSymbolAddress((void**)&we, g_we);
    cudaGetSymbolAddress((void**)&wa, g_wa);
    cudaGetSymbolAddress((void**)&brz, g_brz);

    // ---- one-time prep ----
    build_wrz_kernel<<<(1024 * 768) / 256, 256>>>(W_ih, W_hh);
    build_brz_kernel<<<4, 256>>>(b_ih, b_hh);
    cvt_kernel<<<(512 * 256) / 256, 256>>>(wihn, W_ih + 1024 * 256, 512 * 256);
    cvt_kernel<<<(512 * 512) / 256, 256>>>(whhn, W_hh + 1024 * 512, 512 * 512);
    cvt_kernel<<<(512 * 512) / 256, 256>>>(wo, W_out, 512 * 512);
    cvt_kernel<<<(256 * 512) / 256, 256>>>(we, W_emb, 256 * 512);
    cvt_kernel<<<(512 * 512) / 256, 256>>>(wa, W_agent, 512 * 512);
    cvt_kernel<<<(Bdim * 512) / 256, 256>>>(xbf, x, Bdim * 512);
    init_e0_kernel<<<(Bdim * 256) / 256, 256>>>(sos);

    // h0 = x @ Wa^T + ba (fp32 master + bf16 into A'[0] h-slot)
    gemm_bf<4><<<dim3(4, 32), 128>>>(xbf, 512, wa, 512, b_agent,
                                     hbuf0, 512, abf0 + 256, 768);

    for (int l = 0; l < Ldim; l++) {
        __nv_bfloat16* Ain  = (l & 1) ? abf1 : abf0;
        __nv_bfloat16* Anxt = (l & 1) ? abf0 : abf1;
        float* hin  = (l & 1) ? hbuf1 : hbuf0;
        float* hout = (l & 1) ? hbuf0 : hbuf1;

        // r,z (summed): [e|h] @ Wrz^T + (b_ih+b_hh)   K=768, 256 blocks
        gemm_bf<4><<<dim3(8, 32), 128>>>(Ain, 768, wrz, 768, brz,
                                         grz, 1024, (__nv_bfloat16*)0, 0);
        // i_n = e @ Wih_n^T + b_ih_n                  K=256, 256 blocks
        gemm_bf<2><<<dim3(4, 64), 128>>>(Ain, 768, wihn, 256, b_ih + 1024,
                                         inb, 512, (__nv_bfloat16*)0, 0);
        // h_n GEMM + fused GRU -> hout fp32 + Anxt h-slot bf16 (256 blocks)
        gemm_hn_gru<<<dim3(4, 64), 128>>>(Ain + 256, whhn, b_hh + 1024,
                                          grz, inb, hin, hout, Anxt);
        // logits = h_t @ W_out^T + b_out              K=512, 256 blocks
        gemm_bf<2><<<dim3(4, 64), 128>>>(Anxt + 256, 768, wo, 512, b_out,
                                         lbuf, 512, (__nv_bfloat16*)0, 0);
        // base-2 gumbel softmax + analytic entropy (+ bf16 sample)
        softmax_kernel<<<Bdim / 8, 256>>>(
            lbuf, noise + (size_t)l * Bdim * 512, out, ent, sbf, l);
        // e_{l+1} = sample @ W_emb^T + b_emb -> Anxt e-slot (128 blocks)
        gemm_bf<2><<<dim3(2, 64), 128>>>(sbf, 512, we, 512, b_emb,
                                         (float*)0, 0, Anxt, 768);
    }
    (void)in_sizes; (void)n_in; (void)out_size;
}

// round 11
// speedup vs baseline: 1.2125x; 1.0831x over previous
#include <cuda_runtime.h>
#include <cuda_bf16.h>
#include <math.h>
#include <stdint.h>

#define Bdim 4096
#define Ldim 32
#define LOG2E 1.4426950408889634f

// ---------------- scratch (device globals; no allocation allowed) ----------
__device__ float         g_h[2][(size_t)Bdim * 512];       // fp32 hidden
__device__ __nv_bfloat16 g_abf[2][(size_t)Bdim * 768];     // [e | h] bf16
__device__ float         g_grz[(size_t)Bdim * 1024];
__device__ float         g_in[(size_t)Bdim * 512];
__device__ float         g_logits[(size_t)Bdim * 512];
__device__ __nv_bfloat16 g_xbf[(size_t)Bdim * 512];
__device__ __nv_bfloat16 g_wrz[1024 * 768];
__device__ __nv_bfloat16 g_wihn[512 * 256];
__device__ __nv_bfloat16 g_whhn[512 * 512];
__device__ __nv_bfloat16 g_wo[512 * 512];
__device__ __nv_bfloat16 g_we[256 * 512];
__device__ __nv_bfloat16 g_wa[512 * 512];
__device__ float         g_brz[1024];

__device__ __forceinline__ float sigm(float x) { return 1.f / (1.f + expf(-x)); }

#define MMA_BF16(d, a, b) \
    asm volatile("mma.sync.aligned.m16n8k16.row.col.f32.bf16.bf16.f32 " \
        "{%0,%1,%2,%3}, {%4,%5,%6,%7}, {%8,%9}, {%0,%1,%2,%3};" \
        : "+f"((d)[0]), "+f"((d)[1]), "+f"((d)[2]), "+f"((d)[3]) \
        : "r"((a)[0]), "r"((a)[1]), "r"((a)[2]), "r"((a)[3]), \
          "r"((b)[0]), "r"((b)[1]))

#define LDM_X4(d, addr) \
    asm volatile("ldmatrix.sync.aligned.m8n8.x4.shared.b16 {%0,%1,%2,%3}, [%4];" \
        : "=r"((d)[0]), "=r"((d)[1]), "=r"((d)[2]), "=r"((d)[3]) : "r"(addr))

__device__ __forceinline__ void cp16(uint32_t dst, const void* src) {
    asm volatile("cp.async.cg.shared.global [%0], [%1], 16;" :: "r"(dst), "l"(src) : "memory");
}
#define CP_COMMIT  asm volatile("cp.async.commit_group;" ::: "memory")
#define CP_WAIT2   asm volatile("cp.async.wait_group 2;" ::: "memory")

#define SWZ(r, c) ((uint32_t)((((r) << 2) + ((c) ^ (((r) >> 1) & 3))) << 4))

// ---------------- single segmented prep kernel ------------------------------
// [0,786432) wrz | wihn | whhn | wo | we | wa | xbf | e0 | brz
__global__ void prep_all(
    const float* __restrict__ x, const float* __restrict__ Wih,
    const float* __restrict__ Whh, const float* __restrict__ bih,
    const float* __restrict__ bhh, const float* __restrict__ Wo,
    const float* __restrict__ We, const float* __restrict__ Wa,
    const float* __restrict__ sos)
{
    size_t i = (size_t)blockIdx.x * 256 + threadIdx.x;
    if (i < 786432) {                       // wrz [1024 x 768]
        int g = (int)(i / 768), c = (int)(i % 768);
        float v = (c < 256) ? Wih[g * 256 + c] : Whh[g * 512 + (c - 256)];
        g_wrz[i] = __float2bfloat16_rn(v);
    } else if (i < 917504) {                // wihn
        size_t t = i - 786432;
        g_wihn[t] = __float2bfloat16_rn(Wih[1024 * 256 + t]);
    } else if (i < 1179648) {               // whhn
        size_t t = i - 917504;
        g_whhn[t] = __float2bfloat16_rn(Whh[1024 * 512 + t]);
    } else if (i < 1441792) {               // wo
        size_t t = i - 1179648;
        g_wo[t] = __float2bfloat16_rn(Wo[t]);
    } else if (i < 1572864) {               // we
        size_t t = i - 1441792;
        g_we[t] = __float2bfloat16_rn(We[t]);
    } else if (i < 1835008) {               // wa
        size_t t = i - 1572864;
        g_wa[t] = __float2bfloat16_rn(Wa[t]);
    } else if (i < 3932160) {               // xbf
        size_t t = i - 1835008;
        g_xbf[t] = __float2bfloat16_rn(x[t]);
    } else if (i < 4980736) {               // e0 broadcast
        size_t t = i - 3932160;
        int b = (int)(t >> 8), c = (int)(t & 255);
        g_abf[0][(size_t)b * 768 + c] = __float2bfloat16_rn(sos[c]);
    } else if (i < 4981760) {               // brz
        size_t t = i - 4980736;
        g_brz[t] = bih[t] + bhh[t];
    }
}

// =================== GEMM mainloop (device function) ========================
template<int MFR>
__device__ __forceinline__ void gemm_mainloop(
    char* smem, int tid,
    const __nv_bfloat16* __restrict__ A, int lda,
    const __nv_bfloat16* __restrict__ W, int ldw, int KB,
    int m0, int n0, float acc[MFR][8][4])
{
    constexpr int AS = MFR * 2048;
    constexpr int SS = AS + 8192;
    const int wid = tid >> 5, lane = tid & 31;
    const int wm = wid & 1, wn = wid >> 1;
    const uint32_t smbase = (uint32_t)__cvta_generic_to_shared(smem);

#pragma unroll
    for (int a_ = 0; a_ < MFR; a_++)
#pragma unroll
        for (int b_ = 0; b_ < 8; b_++)
#pragma unroll
            for (int c_ = 0; c_ < 4; c_++) acc[a_][b_][c_] = 0.f;

    const int cr = tid >> 2, cc = tid & 3;
    auto issue = [&](int kb, int s) {
        uint32_t sb = smbase + (uint32_t)s * SS;
#pragma unroll
        for (int it = 0; it < MFR; ++it) {
            int rr = cr + (it << 5);
            cp16(sb + SWZ(rr, cc), A + (size_t)(m0 + rr) * lda + (kb << 5) + (cc << 3));
        }
#pragma unroll
        for (int it = 0; it < 4; ++it) {
            int rr = cr + (it << 5);
            cp16(sb + AS + SWZ(rr, cc), W + (size_t)(n0 + rr) * ldw + (kb << 5) + (cc << 3));
        }
    };
    const int arow0 = wm * (MFR << 4) + (lane & 7) + (((lane >> 3) & 1) << 3);
    const int acb   = (lane >> 4) & 1;
    const int nrow0 = (wn << 6) + (lane & 7) + (((lane >> 4) & 1) << 3);
    const int bcb   = (lane >> 3) & 1;

    issue(0, 0); CP_COMMIT;
    issue(1, 1); CP_COMMIT;
    issue(2, 2); CP_COMMIT;
#pragma unroll 1
    for (int kb = 0; kb < KB; ++kb) {
        CP_WAIT2;
        __syncthreads();
        if (kb + 3 < KB) issue(kb + 3, (kb + 3) & 3);
        CP_COMMIT;
        uint32_t ab = smbase + (uint32_t)(kb & 3) * SS, bb = ab + AS;
#pragma unroll
        for (int ks = 0; ks < 2; ++ks) {
            uint32_t afr[MFR][4];
#pragma unroll
            for (int mt = 0; mt < MFR; ++mt)
                LDM_X4(afr[mt], ab + SWZ(arow0 + (mt << 4), (ks << 1) + acb));
            uint32_t bfr[8][2];
#pragma unroll
            for (int p = 0; p < 4; ++p) {
                uint32_t t4[4];
                LDM_X4(t4, bb + SWZ(nrow0 + (p << 4), (ks << 1) + bcb));
                bfr[2 * p][0] = t4[0]; bfr[2 * p][1] = t4[1];
                bfr[2 * p + 1][0] = t4[2]; bfr[2 * p + 1][1] = t4[3];
            }
#pragma unroll
            for (int mt = 0; mt < MFR; ++mt)
#pragma unroll
                for (int nt = 0; nt < 8; ++nt)
                    MMA_BF16(acc[mt][nt], afr[mt], bfr[nt]);
        }
    }
}

// ---- generic fp32(+bf16) epilogue ----
template<int MFR>
__device__ __forceinline__ void epi_store(
    float acc[MFR][8][4], int tid,
    const float* __restrict__ bias,
    float* __restrict__ C, int ldc,
    __nv_bfloat16* __restrict__ Cbf, int ldcb,
    int m0, int n0)
{
    const int wid = tid >> 5, lane = tid & 31;
    const int wm = wid & 1, wn = wid >> 1;
#pragma unroll
    for (int mt = 0; mt < MFR; ++mt) {
#pragma unroll
        for (int nt = 0; nt < 8; ++nt) {
            int row = m0 + wm * (MFR << 4) + (mt << 4) + (lane >> 2);
            int col = n0 + (wn << 6) + (nt << 3) + ((lane & 3) << 1);
            float2 bv = *(const float2*)&bias[col];
            float2 o0 = {acc[mt][nt][0] + bv.x, acc[mt][nt][1] + bv.y};
            float2 o1 = {acc[mt][nt][2] + bv.x, acc[mt][nt][3] + bv.y};
            if (C) {
                *(float2*)&C[(size_t)row * ldc + col] = o0;
                *(float2*)&C[(size_t)(row + 8) * ldc + col] = o1;
            }
            if (Cbf) {
                __nv_bfloat162 p0 = {__float2bfloat16_rn(o0.x), __float2bfloat16_rn(o0.y)};
                __nv_bfloat162 p1 = {__float2bfloat16_rn(o1.x), __float2bfloat16_rn(o1.y)};
                *(__nv_bfloat162*)&Cbf[(size_t)row * ldcb + col] = p0;
                *(__nv_bfloat162*)&Cbf[(size_t)(row + 8) * ldcb + col] = p1;
            }
        }
    }
}

// ======================= generic bf16 GEMM ==================================
template<int MFR>
__global__ __launch_bounds__(128, 2) void gemm_bf(
    const __nv_bfloat16* __restrict__ A, int lda,
    const __nv_bfloat16* __restrict__ W, int K,
    const float* __restrict__ bias,
    float* __restrict__ C, int ldc,
    __nv_bfloat16* __restrict__ Cbf, int ldcb)
{
    __shared__ __align__(1024) char smem[(MFR * 2048 + 8192) * 4];
    const int tid = threadIdx.x;
    const int m0 = blockIdx.y * (MFR << 5), n0 = blockIdx.x << 7;
    float acc[MFR][8][4];
    gemm_mainloop<MFR>(smem, tid, A, lda, W, K, K >> 5, m0, n0, acc);
    epi_store<MFR>(acc, tid, bias, C, ldc, Cbf, ldcb, m0, n0);
}

// ================= merged gates kernel: rz (256 jobs) + i_n (256 jobs) =====
__global__ __launch_bounds__(128, 2) void gates_kernel(
    const __nv_bfloat16* __restrict__ Ain,   // [B,768] bf16
    const __nv_bfloat16* __restrict__ wrz,   // [1024,768]
    const float* __restrict__ brz,
    const __nv_bfloat16* __restrict__ wihn,  // [512,256]
    const float* __restrict__ bihn,
    float* __restrict__ grz, float* __restrict__ inb)
{
    __shared__ __align__(1024) char smem[(4 * 2048 + 8192) * 4];
    const int tid = threadIdx.x;
    const int j = blockIdx.x;
    if (j < 256) {
        int m0 = (j >> 3) << 7, n0 = (j & 7) << 7;
        float acc[4][8][4];
        gemm_mainloop<4>(smem, tid, Ain, 768, wrz, 768, 24, m0, n0, acc);
        epi_store<4>(acc, tid, brz, grz, 1024, (__nv_bfloat16*)0, 0, m0, n0);
    } else {
        int t = j - 256;
        int m0 = (t >> 2) << 6, n0 = (t & 3) << 7;
        float acc[2][8][4];
        gemm_mainloop<2>(smem, tid, Ain, 768, wihn, 256, 8, m0, n0, acc);
        epi_store<2>(acc, tid, bihn, inb, 512, (__nv_bfloat16*)0, 0, m0, n0);
    }
}

// ================= h_n GEMM with fused GRU update ===========================
__global__ __launch_bounds__(128, 2) void gemm_hn_gru(
    const __nv_bfloat16* __restrict__ A,    // h bf16 (ld 768)
    const __nv_bfloat16* __restrict__ W,    // Whh_n [512,512]
    const float* __restrict__ bias,         // b_hh_n
    const float* __restrict__ grz,          // [B,1024] r|z (biased)
    const float* __restrict__ inb,          // [B,512] i_n (+b_ih_n)
    const float* __restrict__ hin,          // [B,512] fp32
    float* __restrict__ hout,
    __nv_bfloat16* __restrict__ habf)       // Anxt base; h at +256, ld 768
{
    __shared__ __align__(1024) char smem[(2 * 2048 + 8192) * 4];   // 48K
    const int tid = threadIdx.x, wid = tid >> 5, lane = tid & 31;
    const int wm = wid & 1, wn = wid >> 1;
    const int m0 = blockIdx.y << 6, n0 = blockIdx.x << 7;

    float acc[2][8][4];
    gemm_mainloop<2>(smem, tid, A, 768, W, 512, 16, m0, n0, acc);

    __syncthreads();
    float* st = (float*)smem;               // [64][132]
#pragma unroll
    for (int mt = 0; mt < 2; ++mt) {
#pragma unroll
        for (int nt = 0; nt < 8; ++nt) {
            int rl = (wm << 5) + (mt << 4) + (lane >> 2);
            int col = (wn << 6) + (nt << 3) + ((lane & 3) << 1);
            float2 bv = *(const float2*)&bias[n0 + col];
            float2 s0 = {acc[mt][nt][0] + bv.x, acc[mt][nt][1] + bv.y};
            float2 s1 = {acc[mt][nt][2] + bv.x, acc[mt][nt][3] + bv.y};
            *(float2*)&st[rl * 132 + col] = s0;
            *(float2*)&st[(rl + 8) * 132 + col] = s1;
        }
    }
    __syncthreads();

#pragma unroll
    for (int t = 0; t < 16; ++t) {
        int idx = tid + (t << 7);
        int r = idx >> 5, q = idx & 31;
        int rg = m0 + r, jg = n0 + (q << 2);
        float4 hn = *(float4*)&st[r * 132 + (q << 2)];
        float4 rr = *(const float4*)&grz[(size_t)rg * 1024 + jg];
        float4 zz = *(const float4*)&grz[(size_t)rg * 1024 + 512 + jg];
        float4 ii = *(const float4*)&inb[(size_t)rg * 512 + jg];
        float4 hh = *(const float4*)&hin[(size_t)rg * 512 + jg];
        float4 o;
        { float rs = sigm(rr.x), zs = sigm(zz.x);
          o.x = (1.f - zs) * tanhf(ii.x + rs * hn.x) + zs * hh.x; }
        { float rs = sigm(rr.y), zs = sigm(zz.y);
          o.y = (1.f - zs) * tanhf(ii.y + rs * hn.y) + zs * hh.y; }
        { float rs = sigm(rr.z), zs = sigm(zz.z);
          o.z = (1.f - zs) * tanhf(ii.z + rs * hn.z) + zs * hh.z; }
        { float rs = sigm(rr.w), zs = sigm(zz.w);
          o.w = (1.f - zs) * tanhf(ii.w + rs * hn.w) + zs * hh.w; }
        *(float4*)&hout[(size_t)rg * 512 + jg] = o;
        __nv_bfloat162 p0 = {__float2bfloat16_rn(o.x), __float2bfloat16_rn(o.y)};
        __nv_bfloat162 p1 = {__float2bfloat16_rn(o.z), __float2bfloat16_rn(o.w)};
        __nv_bfloat162* dst = (__nv_bfloat162*)(habf + (size_t)rg * 768 + 256 + jg);
        dst[0] = p0; dst[1] = p1;
    }
}

// ========= fused base-2 gumbel softmax + entropy + emb GEMM =================
// Block = 16 batch rows, 128 thr, grid 256. We stages prefetch under softmax.
// dyn smem: [0,16K) sample slabs (16 x 1KB); [16K,80K) 4 x 16KB We stages.
__global__ __launch_bounds__(128, 2) void softemb(
    const float* __restrict__ lbuf, const float* __restrict__ u,
    const __nv_bfloat16* __restrict__ we, const float* __restrict__ be,
    float* __restrict__ seq, float* __restrict__ ent,
    __nv_bfloat16* __restrict__ Ebf, int l)
{
    extern __shared__ __align__(1024) char dsm[];
    const int tid = threadIdx.x, wid = tid >> 5, lane = tid & 31;
    const int b0 = blockIdx.x << 4;
    const uint32_t smbase = (uint32_t)__cvta_generic_to_shared(dsm);
    const uint32_t sB = smbase + 16384u;
    const int cr = tid >> 2, cc = tid & 3;

    auto issueWe = [&](int kb, int s) {
        uint32_t sb = sB + ((uint32_t)s << 14);
#pragma unroll
        for (int it = 0; it < 8; ++it) {
            int rr = cr + (it << 5);
            cp16(sb + SWZ(rr, cc), we + (size_t)rr * 512 + (kb << 5) + (cc << 3));
        }
    };
    issueWe(0, 0); CP_COMMIT;
    issueWe(1, 1); CP_COMMIT;
    issueWe(2, 2); CP_COMMIT;

    // ---- softmax: warp wid handles rows wid*4..wid*4+3 ----
#pragma unroll 1
    for (int rr = 0; rr < 4; ++rr) {
        int row = (wid << 2) + rr;
        int gb = b0 + row;
        const float* lrow = lbuf + (size_t)gb * 512;
        const float* urow = u + (size_t)gb * 512;
        float v[16];
        float m = -INFINITY;
#pragma unroll
        for (int i = 0; i < 16; ++i) {
            float uu = __ldg(urow + lane + 32 * i);
            float s = __log2f(-__log2f(uu));
            v[i] = fmaf(lrow[lane + 32 * i], LOG2E, -s);
            m = fmaxf(m, v[i]);
        }
#pragma unroll
        for (int o = 16; o; o >>= 1) m = fmaxf(m, __shfl_xor_sync(0xffffffffu, m, o));
        float sum = 0.f, ews = 0.f;
#pragma unroll
        for (int i = 0; i < 16; ++i) {
            float w = v[i] - m;
            float e = exp2f(w);
            v[i] = e;
            sum += e;
            ews = fmaf(e, w, ews);
        }
#pragma unroll
        for (int o = 16; o; o >>= 1) {
            sum += __shfl_xor_sync(0xffffffffu, sum, o);
            ews += __shfl_xor_sync(0xffffffffu, ews, o);
        }
        float inv = 1.f / sum;
        float* srow = seq + ((size_t)gb * Ldim + l) * 512;
#pragma unroll
        for (int i = 0; i < 16; ++i) {
            float p = v[i] * inv;
            srow[lane + 32 * i] = p;
            uint32_t off = ((uint32_t)i << 10) + SWZ(row, (lane >> 3) & 3)
                           + ((lane & 7) << 1);
            *(__nv_bfloat16*)(dsm + off) = __float2bfloat16_rn(p);
        }
        if (lane == 0)
            ent[(size_t)gb * Ldim + l] = __log2f(sum) - ews * inv;
    }
    __syncthreads();

    // ---- emb GEMM: sample[16,512] @ We[256,512]^T; warp = 64 N-cols ----
    float acc2[8][4];
#pragma unroll
    for (int b_ = 0; b_ < 8; b_++)
#pragma unroll
        for (int c_ = 0; c_ < 4; c_++) acc2[b_][c_] = 0.f;
    const int arowe = (lane & 7) + (((lane >> 3) & 1) << 3);
    const int acb = (lane >> 4) & 1, bcb = (lane >> 3) & 1;
    const int nrowe = (wid << 6) + (lane & 7) + (((lane >> 4) & 1) << 3);
#pragma unroll 1
    for (int kb = 0; kb < 16; ++kb) {
        CP_WAIT2;
        __syncthreads();
        if (kb + 3 < 16) issueWe(kb + 3, (kb + 3) & 3);
        CP_COMMIT;
        uint32_t ab = smbase + ((uint32_t)kb << 10);
        uint32_t bb = sB + ((uint32_t)(kb & 3) << 14);
#pragma unroll
        for (int ks = 0; ks < 2; ++ks) {
            uint32_t afr[4];
            LDM_X4(afr, ab + SWZ(arowe, (ks << 1) + acb));
            uint32_t bfr[8][2];
#pragma unroll
            for (int p = 0; p < 4; ++p) {
                uint32_t t4[4];
                LDM_X4(t4, bb + SWZ(nrowe + (p << 4), (ks << 1) + bcb));
                bfr[2 * p][0] = t4[0]; bfr[2 * p][1] = t4[1];
                bfr[2 * p + 1][0] = t4[2]; bfr[2 * p + 1][1] = t4[3];
            }
#pragma unroll
            for (int nt = 0; nt < 8; ++nt)
                MMA_BF16(acc2[nt], afr, bfr[nt]);
        }
    }
#pragma unroll
    for (int nt = 0; nt < 8; ++nt) {
        int col = (wid << 6) + (nt << 3) + ((lane & 3) << 1);
        int row = b0 + (lane >> 2);
        float2 bv = *(const float2*)&be[col];
        __nv_bfloat162 p0 = {__float2bfloat16_rn(acc2[nt][0] + bv.x),
                             __float2bfloat16_rn(acc2[nt][1] + bv.y)};
        __nv_bfloat162 p1 = {__float2bfloat16_rn(acc2[nt][2] + bv.x),
                             __float2bfloat16_rn(acc2[nt][3] + bv.y)};
        *(__nv_bfloat162*)&Ebf[(size_t)row * 768 + col] = p0;
        *(__nv_bfloat162*)&Ebf[(size_t)(row + 8) * 768 + col] = p1;
    }
}

// ======================= host launcher ======================================
extern "C" void kernel_launch(void* const* d_in, const int* in_sizes, int n_in,
                              void* d_out, int out_size)
{
    const float* x       = (const float*)d_in[0];
    const float* noise   = (const float*)d_in[1];
    const float* W_agent = (const float*)d_in[2];
    const float* b_agent = (const float*)d_in[3];
    const float* W_ih    = (const float*)d_in[4];
    const float* W_hh    = (const float*)d_in[5];
    const float* b_ih    = (const float*)d_in[6];
    const float* b_hh    = (const float*)d_in[7];
    const float* W_out   = (const float*)d_in[8];
    const float* b_out   = (const float*)d_in[9];
    const float* W_emb   = (const float*)d_in[10];
    const float* b_emb   = (const float*)d_in[11];
    const float* sos     = (const float*)d_in[12];

    float* out = (float*)d_out;
    float* ent = out + (size_t)Bdim * Ldim * 512;

    float *hbuf0, *grz, *inb, *lbuf, *brz;
    __nv_bfloat16 *abf0, *xbf, *wrz, *wihn, *whhn, *wo, *we, *wa;
    cudaGetSymbolAddress((void**)&hbuf0, g_h);
    float* hbuf1 = hbuf0 + (size_t)Bdim * 512;
    cudaGetSymbolAddress((void**)&abf0, g_abf);
    __nv_bfloat16* abf1 = abf0 + (size_t)Bdim * 768;
    cudaGetSymbolAddress((void**)&grz, g_grz);
    cudaGetSymbolAddress((void**)&inb, g_in);
    cudaGetSymbolAddress((void**)&lbuf, g_logits);
    cudaGetSymbolAddress((void**)&xbf, g_xbf);
    cudaGetSymbolAddress((void**)&wrz, g_wrz);
    cudaGetSymbolAddress((void**)&wihn, g_wihn);
    cudaGetSymbolAddress((void**)&whhn, g_whhn);
    cudaGetSymbolAddress((void**)&wo, g_wo);
    cudaGetSymbolAddress((void**)&we, g_we);
    cudaGetSymbolAddress((void**)&wa, g_wa);
    cudaGetSymbolAddress((void**)&brz, g_brz);

    cudaFuncSetAttribute(softemb, cudaFuncAttributeMaxDynamicSharedMemorySize, 81920);

    // ---- one-time prep (single kernel) ----
    prep_all<<<19460, 256>>>(x, W_ih, W_hh, b_ih, b_hh, W_out, W_emb, W_agent, sos);

    // h0 = x @ Wa^T + ba (fp32 master + bf16 into A'[0] h-slot)
    gemm_bf<4><<<dim3(4, 32), 128>>>(xbf, 512, wa, 512, b_agent,
                                     hbuf0, 512, abf0 + 256, 768);

    for (int l = 0; l < Ldim; l++) {
        __nv_bfloat16* Ain  = (l & 1) ? abf1 : abf0;
        __nv_bfloat16* Anxt = (l & 1) ? abf0 : abf1;
        float* hin  = (l & 1) ? hbuf1 : hbuf0;
        float* hout = (l & 1) ? hbuf0 : hbuf1;

        // rz + i_n merged (512 blocks)
        gates_kernel<<<512, 128>>>(Ain, wrz, brz, wihn, b_ih + 1024, grz, inb);
        // h_n GEMM + fused GRU -> hout fp32 + Anxt h-slot bf16 (256 blocks)
        gemm_hn_gru<<<dim3(4, 64), 128>>>(Ain + 256, whhn, b_hh + 1024,
                                          grz, inb, hin, hout, Anxt);
        // logits = h_t @ W_out^T + b_out (256 blocks)
        gemm_bf<2><<<dim3(4, 64), 128>>>(Anxt + 256, 768, wo, 512, b_out,
                                         lbuf, 512, (__nv_bfloat16*)0, 0);
        // softmax + entropy + emb -> out, ent, Anxt e-slot (256 blocks)
        softemb<<<256, 128, 81920>>>(
            lbuf, noise + (size_t)l * Bdim * 512, we, b_emb, out, ent, Anxt, l);
    }
    (void)in_sizes; (void)n_in; (void)out_size;
}